// round 13
// baseline (speedup 1.0000x reference)
#include <cuda_runtime.h>
#include <cuda_bf16.h>
#include <cuda_fp16.h>
#include <stdint.h>

#define N_NODES 50000
#define N_EDGES 800000
#define D 256
#define F 64
#define LN_EPS 1e-5f
#define TE 64
#define TN 64
#define NT_EDGE (N_EDGES / TE)    // 12500
#define EDGE_GRID 148

// ---------------- device scratch ----------------
__device__ float g_Wc[D * D];            // fp32 (W_le @ W_e2), [n][k]
__device__ float g_bc[D];                // W_le @ b_e2
// fragment-packed fp16 weights (hi only): [k16-slice][ntile(32)][lane(32)] = {h0,h1}
__device__ uint2 g_We1_f[4 * 1024];      // K=64  -> 4 slices  (32 KB)
__device__ uint2 g_Wc_f[16 * 1024];      // K=256 -> 16 slices (128 KB)
__device__ uint2 g_Wg1_f[16 * 1024];
__device__ uint2 g_Wg2_f[16 * 1024];
__device__ __align__(16) float g_aggr[(size_t)N_NODES * D];
__device__ int g_idx_is64;
__device__ int g_srcs[N_EDGES], g_dsts[N_EDGES];

// ---------------- low-level helpers ----------------
__device__ __forceinline__ void red_add_v4(float* p, float4 v) {
    asm volatile("red.global.add.v4.f32 [%0], {%1,%2,%3,%4};"
                 :: "l"(p), "f"(v.x), "f"(v.y), "f"(v.z), "f"(v.w) : "memory");
}
__device__ __forceinline__ uint32_t smem_u32(const void* p) {
    return (uint32_t)__cvta_generic_to_shared(p);
}
__device__ __forceinline__ void cpasync16(uint32_t dst, const void* src) {
    asm volatile("cp.async.cg.shared.global [%0], [%1], 16;" :: "r"(dst), "l"(src));
}
__device__ __forceinline__ void cp_commit() { asm volatile("cp.async.commit_group;"); }
__device__ __forceinline__ void cp_wait0()  { asm volatile("cp.async.wait_group 0;"); }

__device__ __forceinline__ void ldsm4(uint32_t* r, uint32_t addr) {
    asm volatile("ldmatrix.sync.aligned.m8n8.x4.shared.b16 {%0,%1,%2,%3}, [%4];"
                 : "=r"(r[0]), "=r"(r[1]), "=r"(r[2]), "=r"(r[3]) : "r"(addr));
}
__device__ __forceinline__ void mma_f16(float* c,
    uint32_t a0, uint32_t a1, uint32_t a2, uint32_t a3, uint32_t b0, uint32_t b1) {
    asm volatile("mma.sync.aligned.m16n8k16.row.col.f32.f16.f16.f32 "
                 "{%0,%1,%2,%3}, {%4,%5,%6,%7}, {%8,%9}, {%0,%1,%2,%3};"
                 : "+f"(c[0]), "+f"(c[1]), "+f"(c[2]), "+f"(c[3])
                 : "r"(a0), "r"(a1), "r"(a2), "r"(a3), "r"(b0), "r"(b1));
}
__device__ __forceinline__ uint32_t pack_f16hi(float a, float b) {
    return (uint32_t)__half_as_ushort(__float2half_rn(a)) |
           ((uint32_t)__half_as_ushort(__float2half_rn(b)) << 16);
}

// contiguous 16KB chunk (2 k16-slices, hi-only) of fragment-packed B -> smem
__device__ __forceinline__ void prefetch_chunk(const uint2* __restrict__ gsrc,
                                               uint32_t b_base, int tid) {
    const uint4* g4 = (const uint4*)gsrc;
    #pragma unroll
    for (int t = 0; t < 4; t++) {
        int i = tid + t * 256;          // 1024 x 16B = 16 KB
        cpasync16(b_base + (uint32_t)i * 16, g4 + i);
    }
    cp_commit();
}

// single-pass 32-k chunk: warp tile 32x64, A fp16 from smem (stride 264), B hi-only
__device__ __forceinline__ void gemm_chunk1(float acc[2][8][4],
    uint32_t ah_u, const uint2* __restrict__ B,
    int k0base, int mg, int ng, int lane)
{
    #pragma unroll
    for (int s = 0; s < 2; s++) {
        uint32_t ahi[2][4];
        int col = k0base + s * 16 + ((lane >> 4) << 3);
        #pragma unroll
        for (int mt = 0; mt < 2; mt++) {
            int row = mg * 32 + mt * 16 + (lane & 15);
            ldsm4(ahi[mt], ah_u + (uint32_t)(row * 264 + col) * 2);
        }
        #pragma unroll
        for (int ni = 0; ni < 8; ni++) {
            uint2 f = B[(s * 32 + ng * 8 + ni) * 32 + lane];
            #pragma unroll
            for (int mt = 0; mt < 2; mt++)
                mma_f16(acc[mt][ni], ahi[mt][0], ahi[mt][1], ahi[mt][2], ahi[mt][3], f.x, f.y);
        }
    }
}

// ---------------- index handling (proven) ----------------
__global__ void detect_idx_kernel(const int* __restrict__ p) {
    __shared__ int acc[256];
    int t = threadIdx.x;
    int v = 0;
    #pragma unroll
    for (int i = 0; i < 4; i++) v |= p[(t * 4 + i) * 2 + 1];
    acc[t] = v;
    __syncthreads();
    for (int s = 128; s; s >>= 1) { if (t < s) acc[t] |= acc[t + s]; __syncthreads(); }
    if (t == 0) g_idx_is64 = (acc[0] == 0) ? 1 : 0;
}
__global__ void convert_idx_kernel(const void* __restrict__ eidx) {
    int i = blockIdx.x * blockDim.x + threadIdx.x;
    if (i >= N_EDGES) return;
    int s, d;
    if (g_idx_is64) {
        const long long* p = (const long long*)eidx;
        s = (int)p[i]; d = (int)p[(size_t)N_EDGES + i];
    } else {
        const int* p = (const int*)eidx;
        s = p[i]; d = p[N_EDGES + i];
    }
    g_srcs[i] = min(max(s, 0), N_NODES - 1);
    g_dsts[i] = min(max(d, 0), N_NODES - 1);
}

// ---------------- prep kernels ----------------
__global__ void prep_Wc(const float* __restrict__ W_le, const float* __restrict__ W_e2) {
    __shared__ float wle[4][256];
    int b = blockIdx.x, t = threadIdx.x;       // 64 blocks
    #pragma unroll
    for (int r = 0; r < 4; r++) wle[r][t] = W_le[(b * 4 + r) * 256 + t];
    __syncthreads();
    float a0 = 0, a1 = 0, a2 = 0, a3 = 0;
    #pragma unroll 4
    for (int j = 0; j < 256; j++) {
        float w = W_e2[j * 256 + t];
        a0 += wle[0][j] * w; a1 += wle[1][j] * w;
        a2 += wle[2][j] * w; a3 += wle[3][j] * w;
    }
    g_Wc[(b * 4 + 0) * 256 + t] = a0;
    g_Wc[(b * 4 + 1) * 256 + t] = a1;
    g_Wc[(b * 4 + 2) * 256 + t] = a2;
    g_Wc[(b * 4 + 3) * 256 + t] = a3;
}
__global__ void prep_bc(const float* __restrict__ W_le, const float* __restrict__ b_e2) {
    __shared__ float red[256];
    int d = blockIdx.x, t = threadIdx.x;       // 256 blocks
    red[t] = W_le[d * 256 + t] * b_e2[t];
    __syncthreads();
    for (int s = 128; s; s >>= 1) { if (t < s) red[t] += red[t + s]; __syncthreads(); }
    if (t == 0) g_bc[d] = red[0];
}
// pack all weights into mma-fragment order (fp16 hi only)
__global__ void pack_frags(const float* __restrict__ We1,
                           const float* __restrict__ Wg1,
                           const float* __restrict__ Wg2) {
    int id = blockIdx.x * 256 + threadIdx.x;     // 53248 total
    const float* W; uint2* dst; int K, rel;
    if (id < 4096)       { W = We1;  dst = g_We1_f; K = 64;  rel = id; }
    else if (id < 20480) { W = g_Wc; dst = g_Wc_f;  K = 256; rel = id - 4096; }
    else if (id < 36864) { W = Wg1;  dst = g_Wg1_f; K = 256; rel = id - 20480; }
    else                 { W = Wg2;  dst = g_Wg2_f; K = 256; rel = id - 36864; }
    int slice = rel >> 10, idx = rel & 1023, nt = idx >> 5, lane = idx & 31;
    int nr = lane >> 2, kq = lane & 3;
    int n = nt * 8 + nr, k0 = slice * 16 + kq * 2;
    uint32_t h0 = pack_f16hi(W[n * K + k0],     W[n * K + k0 + 1]);
    uint32_t h1 = pack_f16hi(W[n * K + k0 + 8], W[n * K + k0 + 9]);
    dst[rel] = make_uint2(h0, h1);
}
__global__ void zero_aggr() {
    size_t i = (size_t)blockIdx.x * blockDim.x + threadIdx.x;
    if (i < (size_t)N_NODES * D / 4)
        ((float4*)g_aggr)[i] = make_float4(0.f, 0.f, 0.f, 0.f);
}

// ---------------- edge kernel: PERSISTENT, weights resident in smem ----------------
// layout: [0,32768) We1_f | [32768,163840) Wc_f | [163840,197632) A (64x264 fp16)
//         emb (32 rows x 260 fp32 = 33280B) aliases A | [197632, +3840) small
#define E_W    0
#define E_WC   32768
#define E_A    163840
#define E_SML  197632
#define EDGE_SMEM_BYTES 201472
#define EMB_STRIDE 260

__global__ __launch_bounds__(256, 1) void edge_kernel(
    const float* __restrict__ x,
    const float* __restrict__ edge_attr,
    const float* __restrict__ b_e1,
    const float* __restrict__ b_le)
{
    extern __shared__ char smem[];
    __half* Ah  = (__half*)(smem + E_A);
    float* emb  = (float*)(smem + E_A);            // aliases A (dead after GEMM2)
    float* pol  = (float*)(smem + E_SML);          // 64
    int*   srcs = (int*)(smem + E_SML + 256);      // 64
    int*   dsts = (int*)(smem + E_SML + 512);      // 64
    float* bcs  = (float*)(smem + E_SML + 768);    // 256
    float* bls  = (float*)(smem + E_SML + 1792);   // 256
    float* be1s = (float*)(smem + E_SML + 2816);   // 256

    const int tid  = threadIdx.x;
    const int lane = tid & 31;
    const int warp = tid >> 5;
    const int mg   = warp >> 2;     // 0..1 (row group of 32)
    const int ng   = warp & 3;      // 0..3 (col group of 64)
    const int nr   = lane >> 2, kq = lane & 3;
    const uint32_t ah_u = smem_u32(Ah);
    const uint2* W1 = (const uint2*)(smem + E_W);
    const uint2* WC = (const uint2*)(smem + E_WC);

    // ---- load ALL weights into smem once ----
    {
        const uint4* w1 = (const uint4*)g_We1_f;   // 2048 uint4
        for (int i = tid; i < 2048; i += 256)
            cpasync16(smem_u32(smem + E_W) + (uint32_t)i * 16, w1 + i);
        const uint4* w2 = (const uint4*)g_Wc_f;    // 8192 uint4
        for (int i = tid; i < 8192; i += 256)
            cpasync16(smem_u32(smem + E_WC) + (uint32_t)i * 16, w2 + i);
        cp_commit();
    }
    bcs[tid]  = g_bc[tid];
    bls[tid]  = b_le[tid];
    be1s[tid] = b_e1[tid];
    cp_wait0();
    __syncthreads();

    float acc[2][8][4];
    #pragma unroll
    for (int a = 0; a < 2; a++)
        #pragma unroll
        for (int b = 0; b < 8; b++)
            #pragma unroll
            for (int c = 0; c < 4; c++) acc[a][b][c] = 0.f;

    // ---- persistent tile loop ----
    #pragma unroll 1
    for (int t = blockIdx.x; t < NT_EDGE; t += EDGE_GRID) {
        const int e0 = t * TE;

        // stage raw (fp16) into A cols 0..63 + metadata
        #pragma unroll
        for (int it = 0; it < 16; it++) {
            int i = tid + it * 256;
            int e = i >> 6, k = i & 63;
            float v = edge_attr[(size_t)(e0 + e) * 65 + 1 + k];
            Ah[e * 264 + k] = __float2half_rn(v);
        }
        if (tid < TE) {
            float p = edge_attr[(size_t)(e0 + tid) * 65];
            pol[tid] = fminf(fmaxf(p, 0.f), 1.f) + 0.01f;
            srcs[tid] = g_srcs[e0 + tid];
            dsts[tid] = g_dsts[e0 + tid];
        }
        __syncthreads();

        // GEMM1: h1 = raw @ We1^T (K=64, resident)
        #pragma unroll
        for (int kc = 0; kc < 2; kc++)
            gemm_chunk1(acc, ah_u, W1 + kc * 2048, kc * 32, mg, ng, lane);
        __syncthreads();

        // h1 = relu(acc + b_e1) -> A (cols = GEMM2 k)
        #pragma unroll
        for (int mt = 0; mt < 2; mt++) {
            int r0 = mg * 32 + mt * 16 + nr, r1 = r0 + 8;
            #pragma unroll
            for (int ni = 0; ni < 8; ni++) {
                int c = ng * 64 + ni * 8 + kq * 2;
                float2 b = *(const float2*)&be1s[c];
                float v0 = fmaxf(acc[mt][ni][0] + b.x, 0.f);
                float v1 = fmaxf(acc[mt][ni][1] + b.y, 0.f);
                float v2 = fmaxf(acc[mt][ni][2] + b.x, 0.f);
                float v3 = fmaxf(acc[mt][ni][3] + b.y, 0.f);
                *(uint32_t*)&Ah[r0 * 264 + c] = pack_f16hi(v0, v1);
                *(uint32_t*)&Ah[r1 * 264 + c] = pack_f16hi(v2, v3);
                acc[mt][ni][0] = acc[mt][ni][1] = acc[mt][ni][2] = acc[mt][ni][3] = 0.f;
            }
        }
        __syncthreads();

        // GEMM2: h2 = h1 @ Wc^T (K=256, resident)
        #pragma unroll
        for (int kc = 0; kc < 8; kc++)
            gemm_chunk1(acc, ah_u, WC + kc * 2048, kc * 32, mg, ng, lane);
        __syncthreads();   // A dead; emb may alias

        // two halves (mt = h): epilogue -> 32-slot emb, then gather+scatter
        #pragma unroll 1
        for (int h = 0; h < 2; h++) {
            {
                int r0 = mg * 32 + h * 16 + nr, r1 = r0 + 8;
                int s0 = mg * 16 + nr,          s1 = s0 + 8;
                float p0 = pol[r0], p1 = pol[r1];
                #pragma unroll
                for (int ni = 0; ni < 8; ni++) {
                    int c = ng * 64 + ni * 8 + kq * 2;
                    float2 bcv = *(const float2*)&bcs[c];
                    float2 blv = *(const float2*)&bls[c];
                    *(float2*)&emb[s0 * EMB_STRIDE + c] =
                        make_float2(p0 * (acc[h][ni][0] + bcv.x) + blv.x,
                                    p0 * (acc[h][ni][1] + bcv.y) + blv.y);
                    *(float2*)&emb[s1 * EMB_STRIDE + c] =
                        make_float2(p1 * (acc[h][ni][2] + bcv.x) + blv.x,
                                    p1 * (acc[h][ni][3] + bcv.y) + blv.y);
                    acc[h][ni][0] = acc[h][ni][1] = acc[h][ni][2] = acc[h][ni][3] = 0.f;
                }
            }
            __syncthreads();
            // scatter: warp handles 4 slots; slot s -> row ((s>>4)<<5) + h*16 + (s&15)
            #pragma unroll
            for (int j = 0; j < 4; j++) {
                int s = warp * 4 + j;
                int r = ((s >> 4) << 5) + h * 16 + (s & 15);
                int si = srcs[r], di = dsts[r];
                const float4* xp = (const float4*)(x + (size_t)si * D);
                float* ap = &g_aggr[(size_t)di * D];
                #pragma unroll
                for (int seg = 0; seg < 2; seg++) {
                    int c4 = lane + seg * 32;
                    float4 ee = *(const float4*)&emb[s * EMB_STRIDE + c4 * 4];
                    float4 xv = xp[c4];
                    float4 m;
                    m.x = fmaxf(xv.x + ee.x, 0.f);
                    m.y = fmaxf(xv.y + ee.y, 0.f);
                    m.z = fmaxf(xv.z + ee.z, 0.f);
                    m.w = fmaxf(xv.w + ee.w, 0.f);
                    red_add_v4(ap + c4 * 4, m);
                }
            }
            __syncthreads();
        }
    }
}

// ---------------- node kernel (64 nodes/block, 1-pass fp16, 2 CTAs/SM) ----------------
#define N_AH   0           // fp16 [64][264] = 33792
#define N_B    33792       // 2 x 16384
#define N_PS   66560       // float2 ps[64][4] = 2048
#define N_SML  68608       // bg1 | lng | lnb | bg2 (4 x 1024)
#define NODE_SMEM_BYTES 72704

__global__ __launch_bounds__(256, 2) void node_kernel(
    const float* __restrict__ x,
    const float* __restrict__ b_g1,
    const float* __restrict__ ln_g,
    const float* __restrict__ ln_b,
    const float* __restrict__ b_g2,
    float* __restrict__ out)
{
    extern __shared__ char smem[];
    __half* Ah = (__half*)(smem + N_AH);
    uint2* Bbuf = (uint2*)(smem + N_B);
    float2* ps  = (float2*)(smem + N_PS);    // [64 rows][4 ngroups]
    float* bg1 = (float*)(smem + N_SML);
    float* lng = (float*)(smem + N_SML + 1024);
    float* lnb = (float*)(smem + N_SML + 2048);
    float* bg2 = (float*)(smem + N_SML + 3072);

    const int tid  = threadIdx.x;
    const int lane = tid & 31;
    const int warp = tid >> 5;
    const int mg   = warp >> 2;
    const int ng   = warp & 3;
    const int nr   = lane >> 2, kq = lane & 3;
    const int n0   = blockIdx.x * TN;
    const uint32_t ah_u = smem_u32(Ah);
    const uint32_t bbase = smem_u32(smem + N_B);

    prefetch_chunk(g_Wg1_f, bbase, tid);

    // stage xin = x + aggr (fp16 hi)
    for (int i = tid; i < TN * D; i += 256) {
        int n = i >> 8, d = i & 255;
        int g = n0 + n;
        float v = 0.f;
        if (g < N_NODES) v = x[(size_t)g * D + d] + g_aggr[(size_t)g * D + d];
        Ah[n * 264 + d] = __float2half_rn(v);
    }
    bg1[tid] = b_g1[tid];
    lng[tid] = ln_g[tid];
    lnb[tid] = ln_b[tid];
    bg2[tid] = b_g2[tid];

    float acc[2][8][4];
    #pragma unroll
    for (int a = 0; a < 2; a++)
        #pragma unroll
        for (int b = 0; b < 8; b++)
            #pragma unroll
            for (int c = 0; c < 4; c++) acc[a][b][c] = 0.f;

    // ---- GEMM1 ----
    #pragma unroll 1
    for (int kc = 0; kc < 8; kc++) {
        cp_wait0();
        __syncthreads();
        if (kc < 7) prefetch_chunk(g_Wg1_f + (kc + 1) * 2048, bbase + ((kc + 1) & 1) * 16384, tid);
        else        prefetch_chunk(g_Wg2_f, bbase, tid);       // chain into GEMM2
        gemm_chunk1(acc, ah_u, Bbuf + (kc & 1) * 2048, kc * 32, mg, ng, lane);
    }

    // ---- bias + partial LN stats (per-warp 64-col partials) ----
    #pragma unroll
    for (int mt = 0; mt < 2; mt++) {
        float sl = 0.f, ql = 0.f, sh = 0.f, qh = 0.f;
        #pragma unroll
        for (int ni = 0; ni < 8; ni++) {
            int c = ng * 64 + ni * 8 + kq * 2;
            float2 b = *(const float2*)&bg1[c];
            float v0 = acc[mt][ni][0] + b.x, v1 = acc[mt][ni][1] + b.y;
            float v2 = acc[mt][ni][2] + b.x, v3 = acc[mt][ni][3] + b.y;
            acc[mt][ni][0] = v0; acc[mt][ni][1] = v1;
            acc[mt][ni][2] = v2; acc[mt][ni][3] = v3;
            sl += v0 + v1; ql += v0 * v0 + v1 * v1;
            sh += v2 + v3; qh += v2 * v2 + v3 * v3;
        }
        #pragma unroll
        for (int off = 1; off <= 2; off <<= 1) {
            sl += __shfl_xor_sync(0xffffffffu, sl, off);
            ql += __shfl_xor_sync(0xffffffffu, ql, off);
            sh += __shfl_xor_sync(0xffffffffu, sh, off);
            qh += __shfl_xor_sync(0xffffffffu, qh, off);
        }
        if (kq == 0) {
            int r0 = mg * 32 + mt * 16 + nr;
            ps[r0 * 4 + ng]       = make_float2(sl, ql);
            ps[(r0 + 8) * 4 + ng] = make_float2(sh, qh);
        }
    }
    __syncthreads();

    // full stats per row, normalize + relu -> A fp16 (overwrites xin)
    float mu[2][2], rs[2][2];
    #pragma unroll
    for (int mt = 0; mt < 2; mt++) {
        int r0 = mg * 32 + mt * 16 + nr;
        #pragma unroll
        for (int h = 0; h < 2; h++) {
            float s = 0.f, q = 0.f;
            #pragma unroll
            for (int g = 0; g < 4; g++) {
                float2 p = ps[(r0 + h * 8) * 4 + g];
                s += p.x; q += p.y;
            }
            float m = s * (1.f / D);
            float v = q * (1.f / D) - m * m;
            mu[mt][h] = m;
            rs[mt][h] = rsqrtf(v + LN_EPS);
        }
    }
    #pragma unroll
    for (int mt = 0; mt < 2; mt++) {
        int r0 = mg * 32 + mt * 16 + nr, r1 = r0 + 8;
        #pragma unroll
        for (int ni = 0; ni < 8; ni++) {
            int c = ng * 64 + ni * 8 + kq * 2;
            float2 g = *(const float2*)&lng[c];
            float2 bb = *(const float2*)&lnb[c];
            float v0 = fmaxf((acc[mt][ni][0] - mu[mt][0]) * rs[mt][0] * g.x + bb.x, 0.f);
            float v1 = fmaxf((acc[mt][ni][1] - mu[mt][0]) * rs[mt][0] * g.y + bb.y, 0.f);
            float v2 = fmaxf((acc[mt][ni][2] - mu[mt][1]) * rs[mt][1] * g.x + bb.x, 0.f);
            float v3 = fmaxf((acc[mt][ni][3] - mu[mt][1]) * rs[mt][1] * g.y + bb.y, 0.f);
            *(uint32_t*)&Ah[r0 * 264 + c] = pack_f16hi(v0, v1);
            *(uint32_t*)&Ah[r1 * 264 + c] = pack_f16hi(v2, v3);
            acc[mt][ni][0] = acc[mt][ni][1] = acc[mt][ni][2] = acc[mt][ni][3] = 0.f;
        }
    }

    // ---- GEMM2 (first sync inside loop orders the A stores above) ----
    #pragma unroll 1
    for (int kc = 0; kc < 8; kc++) {
        cp_wait0();
        __syncthreads();
        if (kc < 7) prefetch_chunk(g_Wg2_f + (kc + 1) * 2048, bbase + ((kc + 1) & 1) * 16384, tid);
        gemm_chunk1(acc, ah_u, Bbuf + (kc & 1) * 2048, kc * 32, mg, ng, lane);
    }

    // ---- epilogue: + b_g2 -> out ----
    #pragma unroll
    for (int mt = 0; mt < 2; mt++) {
        int r0 = mg * 32 + mt * 16 + nr, r1 = r0 + 8;
        int gr0 = n0 + r0, gr1 = n0 + r1;
        #pragma unroll
        for (int ni = 0; ni < 8; ni++) {
            int c = ng * 64 + ni * 8 + kq * 2;
            float2 b = *(const float2*)&bg2[c];
            if (gr0 < N_NODES)
                *(float2*)&out[(size_t)gr0 * D + c] =
                    make_float2(acc[mt][ni][0] + b.x, acc[mt][ni][1] + b.y);
            if (gr1 < N_NODES)
                *(float2*)&out[(size_t)gr1 * D + c] =
                    make_float2(acc[mt][ni][2] + b.x, acc[mt][ni][3] + b.y);
        }
    }
}

// ---------------- launch ----------------
extern "C" void kernel_launch(void* const* d_in, const int* in_sizes, int n_in,
                              void* d_out, int out_size)
{
    const float* x         = (const float*)d_in[0];
    const void*  eidx      = d_in[1];
    const float* edge_attr = (const float*)d_in[2];
    const float* W_e1      = (const float*)d_in[3];
    const float* b_e1      = (const float*)d_in[4];
    const float* W_e2      = (const float*)d_in[5];
    const float* b_e2      = (const float*)d_in[6];
    const float* W_le      = (const float*)d_in[7];
    const float* b_le      = (const float*)d_in[8];
    const float* W_g1      = (const float*)d_in[9];
    const float* b_g1      = (const float*)d_in[10];
    const float* ln_g      = (const float*)d_in[11];
    const float* ln_b      = (const float*)d_in[12];
    const float* W_g2      = (const float*)d_in[13];
    const float* b_g2      = (const float*)d_in[14];
    float*       out       = (float*)d_out;

    cudaFuncSetAttribute(edge_kernel, cudaFuncAttributeMaxDynamicSharedMemorySize, EDGE_SMEM_BYTES);
    cudaFuncSetAttribute(node_kernel, cudaFuncAttributeMaxDynamicSharedMemorySize, NODE_SMEM_BYTES);

    detect_idx_kernel<<<1, 256>>>((const int*)eidx);
    convert_idx_kernel<<<(N_EDGES + 255) / 256, 256>>>(eidx);

    prep_Wc<<<64, 256>>>(W_le, W_e2);
    prep_bc<<<256, 256>>>(W_le, b_e2);
    pack_frags<<<208, 256>>>(W_e1, W_g1, W_g2);
    zero_aggr<<<(N_NODES * D / 4 + 255) / 256, 256>>>();

    edge_kernel<<<EDGE_GRID, 256, EDGE_SMEM_BYTES>>>(x, edge_attr, b_e1, b_le);
    node_kernel<<<(N_NODES + TN - 1) / TN, 256, NODE_SMEM_BYTES>>>(x, b_g1, ln_g, ln_b, b_g2, out);
}

// round 14
// speedup vs baseline: 1.6148x; 1.6148x over previous
#include <cuda_runtime.h>
#include <cuda_bf16.h>
#include <cuda_fp16.h>
#include <stdint.h>

#define N_NODES 50000
#define N_EDGES 800000
#define D 256
#define F 64
#define LN_EPS 1e-5f
#define TE 64
#define TN 64

// ---------------- device scratch ----------------
__device__ float g_Wc[D * D];            // fp32 (W_le @ W_e2), [n][k]
__device__ float g_bc[D];                // W_le @ b_e2
// fragment-packed fp16 weights (hi only): [k16-slice][ntile(32)][lane(32)] = {h0,h1}
__device__ uint2 g_We1_f[4 * 1024];      // K=64  -> 4 slices
__device__ uint2 g_Wc_f[16 * 1024];      // K=256 -> 16 slices
__device__ uint2 g_Wg1_f[16 * 1024];
__device__ uint2 g_Wg2_f[16 * 1024];
__device__ __align__(16) float g_aggr[(size_t)N_NODES * D];
__device__ int g_idx_is64;
__device__ int g_srcs[N_EDGES], g_dsts[N_EDGES];

// ---------------- low-level helpers ----------------
__device__ __forceinline__ void red_add_v4(float* p, float4 v) {
    asm volatile("red.global.add.v4.f32 [%0], {%1,%2,%3,%4};"
                 :: "l"(p), "f"(v.x), "f"(v.y), "f"(v.z), "f"(v.w) : "memory");
}
__device__ __forceinline__ uint32_t smem_u32(const void* p) {
    return (uint32_t)__cvta_generic_to_shared(p);
}
__device__ __forceinline__ void cpasync16(uint32_t dst, const void* src) {
    asm volatile("cp.async.cg.shared.global [%0], [%1], 16;" :: "r"(dst), "l"(src));
}
__device__ __forceinline__ void cp_commit() { asm volatile("cp.async.commit_group;"); }
__device__ __forceinline__ void cp_wait0()  { asm volatile("cp.async.wait_group 0;"); }

__device__ __forceinline__ void ldsm4(uint32_t* r, uint32_t addr) {
    asm volatile("ldmatrix.sync.aligned.m8n8.x4.shared.b16 {%0,%1,%2,%3}, [%4];"
                 : "=r"(r[0]), "=r"(r[1]), "=r"(r[2]), "=r"(r[3]) : "r"(addr));
}
__device__ __forceinline__ void mma_f16(float* c,
    uint32_t a0, uint32_t a1, uint32_t a2, uint32_t a3, uint32_t b0, uint32_t b1) {
    asm volatile("mma.sync.aligned.m16n8k16.row.col.f32.f16.f16.f32 "
                 "{%0,%1,%2,%3}, {%4,%5,%6,%7}, {%8,%9}, {%0,%1,%2,%3};"
                 : "+f"(c[0]), "+f"(c[1]), "+f"(c[2]), "+f"(c[3])
                 : "r"(a0), "r"(a1), "r"(a2), "r"(a3), "r"(b0), "r"(b1));
}
__device__ __forceinline__ uint32_t pack_f16hi(float a, float b) {
    return (uint32_t)__half_as_ushort(__float2half_rn(a)) |
           ((uint32_t)__half_as_ushort(__float2half_rn(b)) << 16);
}

// contiguous 16KB chunk (2 k16-slices, hi-only) of fragment-packed B -> smem
__device__ __forceinline__ void prefetch_chunk(const uint2* __restrict__ gsrc,
                                               uint32_t b_base, int tid) {
    const uint4* g4 = (const uint4*)gsrc;
    #pragma unroll
    for (int t = 0; t < 4; t++) {
        int i = tid + t * 256;          // 1024 x 16B = 16 KB
        cpasync16(b_base + (uint32_t)i * 16, g4 + i);
    }
    cp_commit();
}

// single-pass 32-k chunk: warp tile 32x64, A fp16 from smem (stride 264), B hi-only
__device__ __forceinline__ void gemm_chunk1(float acc[2][8][4],
    uint32_t ah_u, const uint2* __restrict__ B,
    int k0base, int mg, int ng, int lane)
{
    #pragma unroll
    for (int s = 0; s < 2; s++) {
        uint32_t ahi[2][4];
        int col = k0base + s * 16 + ((lane >> 4) << 3);
        #pragma unroll
        for (int mt = 0; mt < 2; mt++) {
            int row = mg * 32 + mt * 16 + (lane & 15);
            ldsm4(ahi[mt], ah_u + (uint32_t)(row * 264 + col) * 2);
        }
        #pragma unroll
        for (int ni = 0; ni < 8; ni++) {
            uint2 f = B[(s * 32 + ng * 8 + ni) * 32 + lane];
            #pragma unroll
            for (int mt = 0; mt < 2; mt++)
                mma_f16(acc[mt][ni], ahi[mt][0], ahi[mt][1], ahi[mt][2], ahi[mt][3], f.x, f.y);
        }
    }
}

// ---------------- index handling (proven) ----------------
__global__ void detect_idx_kernel(const int* __restrict__ p) {
    __shared__ int acc[256];
    int t = threadIdx.x;
    int v = 0;
    #pragma unroll
    for (int i = 0; i < 4; i++) v |= p[(t * 4 + i) * 2 + 1];
    acc[t] = v;
    __syncthreads();
    for (int s = 128; s; s >>= 1) { if (t < s) acc[t] |= acc[t + s]; __syncthreads(); }
    if (t == 0) g_idx_is64 = (acc[0] == 0) ? 1 : 0;
}
__global__ void convert_idx_kernel(const void* __restrict__ eidx) {
    int i = blockIdx.x * blockDim.x + threadIdx.x;
    if (i >= N_EDGES) return;
    int s, d;
    if (g_idx_is64) {
        const long long* p = (const long long*)eidx;
        s = (int)p[i]; d = (int)p[(size_t)N_EDGES + i];
    } else {
        const int* p = (const int*)eidx;
        s = p[i]; d = p[N_EDGES + i];
    }
    g_srcs[i] = min(max(s, 0), N_NODES - 1);
    g_dsts[i] = min(max(d, 0), N_NODES - 1);
}

// ---------------- prep kernels ----------------
__global__ void prep_Wc(const float* __restrict__ W_le, const float* __restrict__ W_e2) {
    __shared__ float wle[4][256];
    int b = blockIdx.x, t = threadIdx.x;       // 64 blocks
    #pragma unroll
    for (int r = 0; r < 4; r++) wle[r][t] = W_le[(b * 4 + r) * 256 + t];
    __syncthreads();
    float a0 = 0, a1 = 0, a2 = 0, a3 = 0;
    #pragma unroll 4
    for (int j = 0; j < 256; j++) {
        float w = W_e2[j * 256 + t];
        a0 += wle[0][j] * w; a1 += wle[1][j] * w;
        a2 += wle[2][j] * w; a3 += wle[3][j] * w;
    }
    g_Wc[(b * 4 + 0) * 256 + t] = a0;
    g_Wc[(b * 4 + 1) * 256 + t] = a1;
    g_Wc[(b * 4 + 2) * 256 + t] = a2;
    g_Wc[(b * 4 + 3) * 256 + t] = a3;
}
__global__ void prep_bc(const float* __restrict__ W_le, const float* __restrict__ b_e2) {
    __shared__ float red[256];
    int d = blockIdx.x, t = threadIdx.x;       // 256 blocks
    red[t] = W_le[d * 256 + t] * b_e2[t];
    __syncthreads();
    for (int s = 128; s; s >>= 1) { if (t < s) red[t] += red[t + s]; __syncthreads(); }
    if (t == 0) g_bc[d] = red[0];
}
// pack all weights into mma-fragment order (fp16 hi only)
__global__ void pack_frags(const float* __restrict__ We1,
                           const float* __restrict__ Wg1,
                           const float* __restrict__ Wg2) {
    int id = blockIdx.x * 256 + threadIdx.x;     // 53248 total
    const float* W; uint2* dst; int K, rel;
    if (id < 4096)       { W = We1;  dst = g_We1_f; K = 64;  rel = id; }
    else if (id < 20480) { W = g_Wc; dst = g_Wc_f;  K = 256; rel = id - 4096; }
    else if (id < 36864) { W = Wg1;  dst = g_Wg1_f; K = 256; rel = id - 20480; }
    else                 { W = Wg2;  dst = g_Wg2_f; K = 256; rel = id - 36864; }
    int slice = rel >> 10, idx = rel & 1023, nt = idx >> 5, lane = idx & 31;
    int nr = lane >> 2, kq = lane & 3;
    int n = nt * 8 + nr, k0 = slice * 16 + kq * 2;
    uint32_t h0 = pack_f16hi(W[n * K + k0],     W[n * K + k0 + 1]);
    uint32_t h1 = pack_f16hi(W[n * K + k0 + 8], W[n * K + k0 + 9]);
    dst[rel] = make_uint2(h0, h1);
}
__global__ void zero_aggr() {
    size_t i = (size_t)blockIdx.x * blockDim.x + threadIdx.x;
    if (i < (size_t)N_NODES * D / 4)
        ((float4*)g_aggr)[i] = make_float4(0.f, 0.f, 0.f, 0.f);
}

// ---------------- edge kernel (64 edges/block, 1-pass fp16, 2 CTAs/SM) ----------------
#define E_AH   0           // fp16 [64][264] = 33792
#define E_B    33792       // 2 x 16384
#define E_SML  66560       // pol 256 | srcs 256 | dsts 256 | bcs 1024 | bls 1024 | be1s 1024
#define EDGE_SMEM_BYTES 70656
#define EMB_STRIDE 260     // fp32 row stride for emb staging (1040B pitch, 16B-aligned)

__global__ __launch_bounds__(256, 2) void edge_kernel(
    const float* __restrict__ x,
    const float* __restrict__ edge_attr,
    const float* __restrict__ b_e1,
    const float* __restrict__ b_le)
{
    extern __shared__ char smem[];
    __half* Ah = (__half*)(smem + E_AH);
    uint2* Bbuf = (uint2*)(smem + E_B);
    float* pol  = (float*)(smem + E_SML);
    int*   srcs = (int*)(smem + E_SML + 256);
    int*   dsts = (int*)(smem + E_SML + 512);
    float* bcs  = (float*)(smem + E_SML + 768);
    float* bls  = (float*)(smem + E_SML + 1792);
    float* be1s = (float*)(smem + E_SML + 2816);

    const int tid  = threadIdx.x;
    const int lane = tid & 31;
    const int warp = tid >> 5;
    const int mg   = warp >> 2;     // 0..1 (row group of 32)
    const int ng   = warp & 3;      // 0..3 (col group of 64)
    const int nr   = lane >> 2, kq = lane & 3;
    const int e0   = blockIdx.x * TE;
    const uint32_t ah_u = smem_u32(Ah);
    const uint32_t bbase = smem_u32(smem + E_B);

    prefetch_chunk(g_We1_f, bbase, tid);          // GEMM1 chunk0 -> buf0

    // stage raw (fp16 hi) into A cols 0..63
    #pragma unroll
    for (int t = 0; t < 16; t++) {
        int i = tid + t * 256;          // 64*64
        int e = i >> 6, k = i & 63;
        float v = edge_attr[(size_t)(e0 + e) * 65 + 1 + k];
        Ah[e * 264 + k] = __float2half_rn(v);
    }
    if (tid < TE) {
        float p = edge_attr[(size_t)(e0 + tid) * 65];
        pol[tid] = fminf(fmaxf(p, 0.f), 1.f) + 0.01f;
        srcs[tid] = g_srcs[e0 + tid];
        dsts[tid] = g_dsts[e0 + tid];
    }
    bcs[tid]  = g_bc[tid];
    bls[tid]  = b_le[tid];
    be1s[tid] = b_e1[tid];

    float acc[2][8][4];
    #pragma unroll
    for (int a = 0; a < 2; a++)
        #pragma unroll
        for (int b = 0; b < 8; b++)
            #pragma unroll
            for (int c = 0; c < 4; c++) acc[a][b][c] = 0.f;

    // ---- GEMM1: h1 = raw @ We1^T (K=64, 2 chunks) ----
    #pragma unroll
    for (int kc = 0; kc < 2; kc++) {
        cp_wait0();
        __syncthreads();
        if (kc == 0) prefetch_chunk(g_We1_f + 2048, bbase + 16384, tid);
        else         prefetch_chunk(g_Wc_f, bbase, tid);        // GEMM2 chunk0 -> buf0
        gemm_chunk1(acc, ah_u, Bbuf + (kc & 1) * 2048, kc * 32, mg, ng, lane);
    }
    __syncthreads();   // all raw reads done before overwrite

    // ---- h1 = relu(acc + b_e1), fp16, store back into A (cols = GEMM2 k) ----
    #pragma unroll
    for (int mt = 0; mt < 2; mt++) {
        int r0 = mg * 32 + mt * 16 + nr, r1 = r0 + 8;
        #pragma unroll
        for (int ni = 0; ni < 8; ni++) {
            int c = ng * 64 + ni * 8 + kq * 2;
            float2 b = *(const float2*)&be1s[c];
            float v0 = fmaxf(acc[mt][ni][0] + b.x, 0.f);
            float v1 = fmaxf(acc[mt][ni][1] + b.y, 0.f);
            float v2 = fmaxf(acc[mt][ni][2] + b.x, 0.f);
            float v3 = fmaxf(acc[mt][ni][3] + b.y, 0.f);
            *(uint32_t*)&Ah[r0 * 264 + c] = pack_f16hi(v0, v1);
            *(uint32_t*)&Ah[r1 * 264 + c] = pack_f16hi(v2, v3);
            acc[mt][ni][0] = acc[mt][ni][1] = acc[mt][ni][2] = acc[mt][ni][3] = 0.f;
        }
    }

    // ---- GEMM2: h2 = h1 @ Wc^T (K=256, 8 chunks, single stream) ----
    #pragma unroll 1
    for (int kc = 0; kc < 8; kc++) {
        cp_wait0();
        __syncthreads();
        if (kc < 7)
            prefetch_chunk(g_Wc_f + (kc + 1) * 2048, bbase + ((kc + 1) & 1) * 16384, tid);
        gemm_chunk1(acc, ah_u, Bbuf + (kc & 1) * 2048, kc * 32, mg, ng, lane);
    }
    __syncthreads();   // A+B reads done; emb may alias the whole region

    // ---- epilogue: emb = pol*(h2 + bc) + bl -> smem (aliases A+B, stride 260) ----
    float* emb = (float*)smem;     // [64][EMB_STRIDE] = 66560 B <= 66560 B
    #pragma unroll
    for (int mt = 0; mt < 2; mt++) {
        int r0 = mg * 32 + mt * 16 + nr, r1 = r0 + 8;
        float p0 = pol[r0], p1 = pol[r1];
        #pragma unroll
        for (int ni = 0; ni < 8; ni++) {
            int c = ng * 64 + ni * 8 + kq * 2;
            float2 bcv = *(const float2*)&bcs[c];
            float2 blv = *(const float2*)&bls[c];
            *(float2*)&emb[r0 * EMB_STRIDE + c] =
                make_float2(p0 * (acc[mt][ni][0] + bcv.x) + blv.x,
                            p0 * (acc[mt][ni][1] + bcv.y) + blv.y);
            *(float2*)&emb[r1 * EMB_STRIDE + c] =
                make_float2(p1 * (acc[mt][ni][2] + bcv.x) + blv.x,
                            p1 * (acc[mt][ni][3] + bcv.y) + blv.y);
        }
    }
    __syncthreads();

    // ---- gather x[src], msg = relu(x+emb), scatter-add ----
    #pragma unroll
    for (int it = 0; it < 8; it++) {
        int r = it * 8 + warp;
        int si = srcs[r], di = dsts[r];
        const float4* xp = (const float4*)(x + (size_t)si * D);
        float* ap = &g_aggr[(size_t)di * D];
        #pragma unroll
        for (int seg = 0; seg < 2; seg++) {
            int c4 = lane + seg * 32;
            float4 ee = *(const float4*)&emb[r * EMB_STRIDE + c4 * 4];
            float4 xv = xp[c4];
            float4 m;
            m.x = fmaxf(xv.x + ee.x, 0.f);
            m.y = fmaxf(xv.y + ee.y, 0.f);
            m.z = fmaxf(xv.z + ee.z, 0.f);
            m.w = fmaxf(xv.w + ee.w, 0.f);
            red_add_v4(ap + c4 * 4, m);
        }
    }
}

// ---------------- node kernel (64 nodes/block, 1-pass fp16, 2 CTAs/SM) ----------------
#define N_AH   0           // fp16 [64][264] = 33792
#define N_B    33792       // 2 x 16384
#define N_PS   66560       // float2 ps[64][4] = 2048
#define N_SML  68608       // bg1 | lng | lnb | bg2 (4 x 1024)
#define NODE_SMEM_BYTES 72704

__global__ __launch_bounds__(256, 2) void node_kernel(
    const float* __restrict__ x,
    const float* __restrict__ b_g1,
    const float* __restrict__ ln_g,
    const float* __restrict__ ln_b,
    const float* __restrict__ b_g2,
    float* __restrict__ out)
{
    extern __shared__ char smem[];
    __half* Ah = (__half*)(smem + N_AH);
    uint2* Bbuf = (uint2*)(smem + N_B);
    float2* ps  = (float2*)(smem + N_PS);    // [64 rows][4 ngroups]
    float* bg1 = (float*)(smem + N_SML);
    float* lng = (float*)(smem + N_SML + 1024);
    float* lnb = (float*)(smem + N_SML + 2048);
    float* bg2 = (float*)(smem + N_SML + 3072);

    const int tid  = threadIdx.x;
    const int lane = tid & 31;
    const int warp = tid >> 5;
    const int mg   = warp >> 2;
    const int ng   = warp & 3;
    const int nr   = lane >> 2, kq = lane & 3;
    const int n0   = blockIdx.x * TN;
    const uint32_t ah_u = smem_u32(Ah);
    const uint32_t bbase = smem_u32(smem + N_B);

    prefetch_chunk(g_Wg1_f, bbase, tid);

    // stage xin = x + aggr (fp16 hi)
    for (int i = tid; i < TN * D; i += 256) {
        int n = i >> 8, d = i & 255;
        int g = n0 + n;
        float v = 0.f;
        if (g < N_NODES) v = x[(size_t)g * D + d] + g_aggr[(size_t)g * D + d];
        Ah[n * 264 + d] = __float2half_rn(v);
    }
    bg1[tid] = b_g1[tid];
    lng[tid] = ln_g[tid];
    lnb[tid] = ln_b[tid];
    bg2[tid] = b_g2[tid];

    float acc[2][8][4];
    #pragma unroll
    for (int a = 0; a < 2; a++)
        #pragma unroll
        for (int b = 0; b < 8; b++)
            #pragma unroll
            for (int c = 0; c < 4; c++) acc[a][b][c] = 0.f;

    // ---- GEMM1 ----
    #pragma unroll 1
    for (int kc = 0; kc < 8; kc++) {
        cp_wait0();
        __syncthreads();
        if (kc < 7) prefetch_chunk(g_Wg1_f + (kc + 1) * 2048, bbase + ((kc + 1) & 1) * 16384, tid);
        else        prefetch_chunk(g_Wg2_f, bbase, tid);       // chain into GEMM2
        gemm_chunk1(acc, ah_u, Bbuf + (kc & 1) * 2048, kc * 32, mg, ng, lane);
    }

    // ---- bias + partial LN stats (per-warp 64-col partials) ----
    #pragma unroll
    for (int mt = 0; mt < 2; mt++) {
        float sl = 0.f, ql = 0.f, sh = 0.f, qh = 0.f;
        #pragma unroll
        for (int ni = 0; ni < 8; ni++) {
            int c = ng * 64 + ni * 8 + kq * 2;
            float2 b = *(const float2*)&bg1[c];
            float v0 = acc[mt][ni][0] + b.x, v1 = acc[mt][ni][1] + b.y;
            float v2 = acc[mt][ni][2] + b.x, v3 = acc[mt][ni][3] + b.y;
            acc[mt][ni][0] = v0; acc[mt][ni][1] = v1;
            acc[mt][ni][2] = v2; acc[mt][ni][3] = v3;
            sl += v0 + v1; ql += v0 * v0 + v1 * v1;
            sh += v2 + v3; qh += v2 * v2 + v3 * v3;
        }
        #pragma unroll
        for (int off = 1; off <= 2; off <<= 1) {
            sl += __shfl_xor_sync(0xffffffffu, sl, off);
            ql += __shfl_xor_sync(0xffffffffu, ql, off);
            sh += __shfl_xor_sync(0xffffffffu, sh, off);
            qh += __shfl_xor_sync(0xffffffffu, qh, off);
        }
        if (kq == 0) {
            int r0 = mg * 32 + mt * 16 + nr;
            ps[r0 * 4 + ng]       = make_float2(sl, ql);
            ps[(r0 + 8) * 4 + ng] = make_float2(sh, qh);
        }
    }
    __syncthreads();

    // full stats per row, normalize + relu -> A fp16 (overwrites xin)
    float mu[2][2], rs[2][2];
    #pragma unroll
    for (int mt = 0; mt < 2; mt++) {
        int r0 = mg * 32 + mt * 16 + nr;
        #pragma unroll
        for (int h = 0; h < 2; h++) {
            float s = 0.f, q = 0.f;
            #pragma unroll
            for (int g = 0; g < 4; g++) {
                float2 p = ps[(r0 + h * 8) * 4 + g];
                s += p.x; q += p.y;
            }
            float m = s * (1.f / D);
            float v = q * (1.f / D) - m * m;
            mu[mt][h] = m;
            rs[mt][h] = rsqrtf(v + LN_EPS);
        }
    }
    #pragma unroll
    for (int mt = 0; mt < 2; mt++) {
        int r0 = mg * 32 + mt * 16 + nr, r1 = r0 + 8;
        #pragma unroll
        for (int ni = 0; ni < 8; ni++) {
            int c = ng * 64 + ni * 8 + kq * 2;
            float2 g = *(const float2*)&lng[c];
            float2 bb = *(const float2*)&lnb[c];
            float v0 = fmaxf((acc[mt][ni][0] - mu[mt][0]) * rs[mt][0] * g.x + bb.x, 0.f);
            float v1 = fmaxf((acc[mt][ni][1] - mu[mt][0]) * rs[mt][0] * g.y + bb.y, 0.f);
            float v2 = fmaxf((acc[mt][ni][2] - mu[mt][1]) * rs[mt][1] * g.x + bb.x, 0.f);
            float v3 = fmaxf((acc[mt][ni][3] - mu[mt][1]) * rs[mt][1] * g.y + bb.y, 0.f);
            *(uint32_t*)&Ah[r0 * 264 + c] = pack_f16hi(v0, v1);
            *(uint32_t*)&Ah[r1 * 264 + c] = pack_f16hi(v2, v3);
            acc[mt][ni][0] = acc[mt][ni][1] = acc[mt][ni][2] = acc[mt][ni][3] = 0.f;
        }
    }

    // ---- GEMM2 (first sync inside loop orders the A stores above) ----
    #pragma unroll 1
    for (int kc = 0; kc < 8; kc++) {
        cp_wait0();
        __syncthreads();
        if (kc < 7) prefetch_chunk(g_Wg2_f + (kc + 1) * 2048, bbase + ((kc + 1) & 1) * 16384, tid);
        gemm_chunk1(acc, ah_u, Bbuf + (kc & 1) * 2048, kc * 32, mg, ng, lane);
    }

    // ---- epilogue: + b_g2 -> out ----
    #pragma unroll
    for (int mt = 0; mt < 2; mt++) {
        int r0 = mg * 32 + mt * 16 + nr, r1 = r0 + 8;
        int gr0 = n0 + r0, gr1 = n0 + r1;
        #pragma unroll
        for (int ni = 0; ni < 8; ni++) {
            int c = ng * 64 + ni * 8 + kq * 2;
            float2 b = *(const float2*)&bg2[c];
            if (gr0 < N_NODES)
                *(float2*)&out[(size_t)gr0 * D + c] =
                    make_float2(acc[mt][ni][0] + b.x, acc[mt][ni][1] + b.y);
            if (gr1 < N_NODES)
                *(float2*)&out[(size_t)gr1 * D + c] =
                    make_float2(acc[mt][ni][2] + b.x, acc[mt][ni][3] + b.y);
        }
    }
}

// ---------------- launch ----------------
extern "C" void kernel_launch(void* const* d_in, const int* in_sizes, int n_in,
                              void* d_out, int out_size)
{
    const float* x         = (const float*)d_in[0];
    const void*  eidx      = d_in[1];
    const float* edge_attr = (const float*)d_in[2];
    const float* W_e1      = (const float*)d_in[3];
    const float* b_e1      = (const float*)d_in[4];
    const float* W_e2      = (const float*)d_in[5];
    const float* b_e2      = (const float*)d_in[6];
    const float* W_le      = (const float*)d_in[7];
    const float* b_le      = (const float*)d_in[8];
    const float* W_g1      = (const float*)d_in[9];
    const float* b_g1      = (const float*)d_in[10];
    const float* ln_g      = (const float*)d_in[11];
    const float* ln_b      = (const float*)d_in[12];
    const float* W_g2      = (const float*)d_in[13];
    const float* b_g2      = (const float*)d_in[14];
    float*       out       = (float*)d_out;

    cudaFuncSetAttribute(edge_kernel, cudaFuncAttributeMaxDynamicSharedMemorySize, EDGE_SMEM_BYTES);
    cudaFuncSetAttribute(node_kernel, cudaFuncAttributeMaxDynamicSharedMemorySize, NODE_SMEM_BYTES);

    detect_idx_kernel<<<1, 256>>>((const int*)eidx);
    convert_idx_kernel<<<(N_EDGES + 255) / 256, 256>>>(eidx);

    prep_Wc<<<64, 256>>>(W_le, W_e2);
    prep_bc<<<256, 256>>>(W_le, b_e2);
    pack_frags<<<208, 256>>>(W_e1, W_g1, W_g2);
    zero_aggr<<<(N_NODES * D / 4 + 255) / 256, 256>>>();

    edge_kernel<<<N_EDGES / TE, 256, EDGE_SMEM_BYTES>>>(x, edge_attr, b_e1, b_le);
    node_kernel<<<(N_NODES + TN - 1) / TN, 256, NODE_SMEM_BYTES>>>(x, b_g1, ln_g, ln_b, b_g2, out);
}